// round 4
// baseline (speedup 1.0000x reference)
#include <cuda_runtime.h>
#include <cstdint>

// Problem constants (fixed shapes for this problem)
#define TT   128
#define NN   50000
#define EE   1600000
#define CIN  16
#define CH   32
#define COUTC 8
#define FULL 0xFFFFFFFFu

// ---------------- scratch (device globals; no runtime allocation) ----------
__device__ int   g_is64;
__device__ int   g_cnt_src[NN];
__device__ int   g_cnt_dst[NN];
__device__ int   g_cursor[NN];
__device__ int   g_off[NN + 1];
__device__ float g_dinv[NN];
__device__ int   g_csr_src[EE];
__device__ float g_csr_w[EE];
__device__ float g_h[NN * CH];
__device__ float g_hR[NN * CH];
__device__ float g_Z[NN * CH];
__device__ float g_AX[(size_t)TT * NN * CIN];   // agg(x_t) for all t : ~410MB

// read edge index element `idx` honoring detected dtype
__device__ __forceinline__ long long edge_at(const void* ei, size_t idx) {
    if (g_is64) return ((const long long*)ei)[idx];
    return (long long)((const int*)ei)[idx];
}

// ---------------- preprocessing ----------------

__global__ void k_zero() {
    int i = blockIdx.x * blockDim.x + threadIdx.x;
    int stride = gridDim.x * blockDim.x;
    if (i == 0) g_is64 = 1;
    for (int j = i; j < NN * CH; j += stride) {
        g_h[j] = 0.f;
        if (j < NN) { g_cnt_src[j] = 0; g_cnt_dst[j] = 0; g_cursor[j] = 0; }
    }
}

// Detect dtype: if buffer is int32 but read as int64, values combine two
// random indices -> almost surely >= NN. Scan first 1024 "int64" values.
__global__ void k_detect(const void* ei) {
    int i = threadIdx.x;  // 1024 threads, 1 block
    long long v = ((const long long*)ei)[i];
    if (v < 0 || v >= NN) atomicExch(&g_is64, 0);
}

__global__ void k_count(const void* __restrict__ ei, int E) {
    int i = blockIdx.x * blockDim.x + threadIdx.x;
    if (i < E) {
        long long s = edge_at(ei, i);
        long long d = edge_at(ei, (size_t)E + i);
        if (s >= 0 && s < NN) atomicAdd(&g_cnt_src[(int)s], 1);
        if (d >= 0 && d < NN) atomicAdd(&g_cnt_dst[(int)d], 1);
    }
}

__global__ void k_dinv() {
    int n = blockIdx.x * blockDim.x + threadIdx.x;
    if (n < NN) {
        int d = g_cnt_src[n];
        g_dinv[n] = (d > 0) ? rsqrtf((float)d) : 0.f;
    }
}

// exclusive prefix sum of g_cnt_dst -> g_off  (single block, 1024 threads)
__global__ void k_scan() {
    __shared__ int s[1024];
    __shared__ int carry_s;
    int tid = threadIdx.x;
    if (tid == 0) carry_s = 0;
    __syncthreads();
    for (int base = 0; base < NN; base += 1024) {
        int i = base + tid;
        int v = (i < NN) ? g_cnt_dst[i] : 0;
        s[tid] = v;
        __syncthreads();
        for (int off = 1; off < 1024; off <<= 1) {
            int x = (tid >= off) ? s[tid - off] : 0;
            __syncthreads();
            s[tid] += x;
            __syncthreads();
        }
        if (i < NN) g_off[i] = carry_s + s[tid] - v;   // exclusive
        __syncthreads();
        if (tid == 0) carry_s += s[1023];
        __syncthreads();
    }
    if (threadIdx.x == 0) g_off[NN] = carry_s;
}

__global__ void k_fill(const void* __restrict__ ei, int E) {
    int i = blockIdx.x * blockDim.x + threadIdx.x;
    if (i < E) {
        long long sl = edge_at(ei, i);
        long long dl = edge_at(ei, (size_t)E + i);
        if (sl < 0 || sl >= NN || dl < 0 || dl >= NN) return;
        int s = (int)sl, d = (int)dl;
        int pos = g_off[d] + atomicAdd(&g_cursor[d], 1);
        g_csr_src[pos] = s;
        g_csr_w[pos]   = -g_dinv[s] * g_dinv[d];
    }
}

// ---------------- time-parallel precompute: AX[t,n,:] = agg(x_t)[n] -------
// block = 256 threads = 8 warps. Each warp: one node, two timesteps.
// lanes 0..15 -> (t0, ch=lane), lanes 16..31 -> (t0+1, ch=lane-16)
__global__ void __launch_bounds__(256) k_ax(const float* __restrict__ X) {
    int warp = threadIdx.x >> 5, lane = threadIdx.x & 31;
    int tp = blockIdx.x / (NN / 8);
    int nb = blockIdx.x % (NN / 8);
    int n  = nb * 8 + warp;
    int t  = tp * 2 + (lane >> 4);
    int ch = lane & 15;

    int beg = g_off[n], end = g_off[n + 1];
    float a = 0.f;
    for (int k0 = beg; k0 < end; k0 += 32) {
        int idx = k0 + lane;
        int s = 0; float w = 0.f;
        if (idx < end) { s = g_csr_src[idx]; w = g_csr_w[idx]; }
        int cnt = min(32, end - k0);
        for (int i = 0; i < cnt; i++) {
            int   si = __shfl_sync(FULL, s, i);
            float wi = __shfl_sync(FULL, w, i);
            a += wi * X[((size_t)t * NN + si) * CIN + ch];
        }
    }
    g_AX[((size_t)t * NN + n) * CIN + ch] = a;
}

// ---------------- recurrence kernels ----------------
// Warp per node, lane = hidden channel. One coalesced 128B line per edge.

__global__ void __launch_bounds__(512) k_gru_a(
    int t, const float* __restrict__ X,
    const float* __restrict__ Wxz, const float* __restrict__ bxz,
    const float* __restrict__ Whz, const float* __restrict__ bhz,
    const float* __restrict__ Wxr, const float* __restrict__ bxr,
    const float* __restrict__ Whr, const float* __restrict__ bhr)
{
    __shared__ float s_wxz[2 * CIN * CH], s_wxr[2 * CIN * CH];
    __shared__ float s_whz[2 * CH * CH], s_whr[2 * CH * CH];
    __shared__ float s_bz[CH], s_br[CH];
    int tid = threadIdx.x;
    for (int i = tid; i < 2 * CIN * CH; i += blockDim.x) { s_wxz[i] = Wxz[i]; s_wxr[i] = Wxr[i]; }
    for (int i = tid; i < 2 * CH * CH;  i += blockDim.x) { s_whz[i] = Whz[i]; s_whr[i] = Whr[i]; }
    if (tid < CH) { s_bz[tid] = bxz[tid] + bhz[tid]; s_br[tid] = bxr[tid] + bhr[tid]; }
    __syncthreads();

    int lane = tid & 31;
    int gwarp  = blockIdx.x * (blockDim.x >> 5) + (tid >> 5);
    int nwarps = gridDim.x * (blockDim.x >> 5);
    for (int n = gwarp; n < NN; n += nwarps) {
        float hv = g_h[n * CH + lane];
        float xv = 0.f, axv = 0.f;
        if (lane < CIN) {
            xv  = X   [((size_t)t * NN + n) * CIN + lane];
            axv = g_AX[((size_t)t * NN + n) * CIN + lane];
        }
        // a = agg(h)[n, lane]
        int beg = g_off[n], end = g_off[n + 1];
        float av = 0.f;
        for (int k0 = beg; k0 < end; k0 += 32) {
            int idx = k0 + lane;
            int s = 0; float w = 0.f;
            if (idx < end) { s = g_csr_src[idx]; w = g_csr_w[idx]; }
            int cnt = min(32, end - k0);
            for (int i = 0; i < cnt; i++) {
                int   si = __shfl_sync(FULL, s, i);
                float wi = __shfl_sync(FULL, w, i);
                av += wi * g_h[si * CH + lane];
            }
        }
        float z = s_bz[lane], r = s_br[lane];
#pragma unroll
        for (int c = 0; c < CIN; c++) {
            float xc = __shfl_sync(FULL, xv, c);
            float ac = __shfl_sync(FULL, axv, c);
            z += xc * s_wxz[c * CH + lane] + ac * s_wxz[CIN * CH + c * CH + lane];
            r += xc * s_wxr[c * CH + lane] + ac * s_wxr[CIN * CH + c * CH + lane];
        }
#pragma unroll
        for (int c = 0; c < CH; c++) {
            float hc = __shfl_sync(FULL, hv, c);
            float ac = __shfl_sync(FULL, av, c);
            z += hc * s_whz[c * CH + lane] + ac * s_whz[CH * CH + c * CH + lane];
            r += hc * s_whr[c * CH + lane] + ac * s_whr[CH * CH + c * CH + lane];
        }
        z = 1.f / (1.f + __expf(-z));
        r = 1.f / (1.f + __expf(-r));
        g_Z [n * CH + lane] = z;
        g_hR[n * CH + lane] = hv * r;
    }
}

__global__ void __launch_bounds__(512) k_gru_b(
    int t, const float* __restrict__ X,
    const float* __restrict__ Wxh, const float* __restrict__ bxh,
    const float* __restrict__ Whh, const float* __restrict__ bhh,
    const float* __restrict__ fcw, const float* __restrict__ fcb,
    float* __restrict__ out)
{
    __shared__ float s_wxh[2 * CIN * CH];
    __shared__ float s_whh[2 * CH * CH];
    __shared__ float s_fcw[CH * COUTC];
    __shared__ float s_bh[CH];
    __shared__ float s_fcb[COUTC];
    int tid = threadIdx.x;
    for (int i = tid; i < 2 * CIN * CH; i += blockDim.x) s_wxh[i] = Wxh[i];
    for (int i = tid; i < 2 * CH * CH;  i += blockDim.x) s_whh[i] = Whh[i];
    for (int i = tid; i < CH * COUTC;   i += blockDim.x) s_fcw[i] = fcw[i];
    if (tid < CH)    s_bh[tid]  = bxh[tid] + bhh[tid];
    if (tid < COUTC) s_fcb[tid] = fcb[tid];
    __syncthreads();

    int lane = tid & 31;
    int gwarp  = blockIdx.x * (blockDim.x >> 5) + (tid >> 5);
    int nwarps = gridDim.x * (blockDim.x >> 5);
    for (int n = gwarp; n < NN; n += nwarps) {
        float hv  = g_h [n * CH + lane];
        float hrv = g_hR[n * CH + lane];   // h * R  (dense operand of cheb(h*R, Whh))
        float z   = g_Z [n * CH + lane];
        float xv = 0.f, axv = 0.f;
        if (lane < CIN) {
            xv  = X   [((size_t)t * NN + n) * CIN + lane];
            axv = g_AX[((size_t)t * NN + n) * CIN + lane];
        }
        // a = agg(h*R)[n, lane]
        int beg = g_off[n], end = g_off[n + 1];
        float av = 0.f;
        for (int k0 = beg; k0 < end; k0 += 32) {
            int idx = k0 + lane;
            int s = 0; float w = 0.f;
            if (idx < end) { s = g_csr_src[idx]; w = g_csr_w[idx]; }
            int cnt = min(32, end - k0);
            for (int i = 0; i < cnt; i++) {
                int   si = __shfl_sync(FULL, s, i);
                float wi = __shfl_sync(FULL, w, i);
                av += wi * g_hR[si * CH + lane];
            }
        }
        float ht = s_bh[lane];
#pragma unroll
        for (int c = 0; c < CIN; c++) {
            float xc = __shfl_sync(FULL, xv, c);
            float ac = __shfl_sync(FULL, axv, c);
            ht += xc * s_wxh[c * CH + lane] + ac * s_wxh[CIN * CH + c * CH + lane];
        }
#pragma unroll
        for (int c = 0; c < CH; c++) {
            float hrc = __shfl_sync(FULL, hrv, c);   // (h*R) @ Whh[0]
            float ac  = __shfl_sync(FULL, av, c);    // agg(h*R) @ Whh[1]
            ht += hrc * s_whh[c * CH + lane] + ac * s_whh[CH * CH + c * CH + lane];
        }
        ht = tanhf(ht);
        float hn = z * hv + (1.f - z) * ht;
        g_h[n * CH + lane] = hn;

        // out[t,n,:] = hn @ fc_w + fc_b  (lanes 0..7 accumulate)
        float acc = (lane < COUTC) ? s_fcb[lane] : 0.f;
#pragma unroll
        for (int j = 0; j < CH; j++) {
            float hj = __shfl_sync(FULL, hn, j);
            if (lane < COUTC) acc += hj * s_fcw[j * COUTC + lane];
        }
        if (lane < COUTC) out[((size_t)t * NN + n) * COUTC + lane] = acc;
    }
}

// ---------------- launch ----------------
extern "C" void kernel_launch(void* const* d_in, const int* in_sizes, int n_in,
                              void* d_out, int out_size) {
    const float* X   = (const float*)d_in[0];
    const void*  ei  = d_in[1];
    const float* Wxz = (const float*)d_in[2];
    const float* bxz = (const float*)d_in[3];
    const float* Whz = (const float*)d_in[4];
    const float* bhz = (const float*)d_in[5];
    const float* Wxr = (const float*)d_in[6];
    const float* bxr = (const float*)d_in[7];
    const float* Whr = (const float*)d_in[8];
    const float* bhr = (const float*)d_in[9];
    const float* Wxh = (const float*)d_in[10];
    const float* bxh = (const float*)d_in[11];
    const float* Whh = (const float*)d_in[12];
    const float* bhh = (const float*)d_in[13];
    const float* fcw = (const float*)d_in[14];
    const float* fcb = (const float*)d_in[15];
    float* out = (float*)d_out;

    int E = in_sizes[1] / 2;

    // preprocess: dtype detect, degrees, dinv, CSR by dst
    k_zero<<<2048, 256>>>();
    k_detect<<<1, 1024>>>(ei);
    k_count<<<(E + 255) / 256, 256>>>(ei, E);
    k_dinv<<<(NN + 255) / 256, 256>>>();
    k_scan<<<1, 1024>>>();
    k_fill<<<(E + 255) / 256, 256>>>(ei, E);

    // time-parallel agg(x_t) for all t
    k_ax<<<(TT / 2) * (NN / 8), 256>>>(X);

    // sequential GRU recurrence
    for (int t = 0; t < TT; t++) {
        k_gru_a<<<608, 512>>>(t, X, Wxz, bxz, Whz, bhz, Wxr, bxr, Whr, bhr);
        k_gru_b<<<608, 512>>>(t, X, Wxh, bxh, Whh, bhh, fcw, fcb, out);
    }
}

// round 5
// speedup vs baseline: 2.4274x; 2.4274x over previous
#include <cuda_runtime.h>
#include <cstdint>

// Problem constants (fixed shapes for this problem)
#define TT   128
#define NN   50000
#define EE   1600000
#define CIN  16
#define CH   32
#define COUTC 8
#define FULL 0xFFFFFFFFu

#define GETC(v,u) ((u)==0?(v).x:(u)==1?(v).y:(u)==2?(v).z:(v).w)

// ---------------- scratch (device globals; no runtime allocation) ----------
__device__ int   g_is64;
__device__ int   g_cnt_src[NN];
__device__ int   g_cnt_dst[NN];
__device__ int   g_cursor[NN];
__device__ int   g_off[NN + 1];
__device__ float g_dinv[NN];
__device__ int2  g_csr[EE];            // {src, w-bits}
__device__ float g_h[NN * CH];
__device__ float g_hR[NN * CH];
__device__ float g_Z[NN * CH];
__device__ float g_AX[(size_t)TT * NN * CIN];   // agg(x_t) for all t

// read edge index element honoring detected dtype
__device__ __forceinline__ long long edge_at(const void* ei, size_t idx) {
    if (g_is64) return ((const long long*)ei)[idx];
    return (long long)((const int*)ei)[idx];
}

// ---------------- preprocessing ----------------

// zero state + dtype detect (block 0)
__global__ void k_zero(const void* ei) {
    int i = blockIdx.x * blockDim.x + threadIdx.x;
    int stride = gridDim.x * blockDim.x;
    if (blockIdx.x == 0) {
        // detect: int32 data read as int64 packs two random indices -> >= NN
        int bad = 0;
        for (int k = threadIdx.x; k < 1024; k += blockDim.x) {
            long long v = ((const long long*)ei)[k];
            if (v < 0 || v >= NN) bad = 1;
        }
        int anybad = __syncthreads_or(bad);
        if (threadIdx.x == 0) g_is64 = anybad ? 0 : 1;
    }
    for (int j = i; j < NN * CH; j += stride) {
        g_h[j] = 0.f;
        if (j < NN) { g_cnt_src[j] = 0; g_cnt_dst[j] = 0; g_cursor[j] = 0; }
    }
}

__global__ void k_count(const void* __restrict__ ei, int E) {
    int i = blockIdx.x * blockDim.x + threadIdx.x;
    if (i < E) {
        long long s = edge_at(ei, i);
        long long d = edge_at(ei, (size_t)E + i);
        if (s >= 0 && s < NN) atomicAdd(&g_cnt_src[(int)s], 1);
        if (d >= 0 && d < NN) atomicAdd(&g_cnt_dst[(int)d], 1);
    }
}

// exclusive prefix sum of g_cnt_dst -> g_off, plus dinv (single block, 1024 thr)
__global__ void k_scan() {
    __shared__ int s[1024];
    __shared__ int carry_s;
    int tid = threadIdx.x;
    if (tid == 0) carry_s = 0;
    __syncthreads();
    for (int base = 0; base < NN; base += 1024) {
        int i = base + tid;
        int v = (i < NN) ? g_cnt_dst[i] : 0;
        if (i < NN) {
            int dsrc = g_cnt_src[i];
            g_dinv[i] = (dsrc > 0) ? rsqrtf((float)dsrc) : 0.f;
        }
        s[tid] = v;
        __syncthreads();
        for (int off = 1; off < 1024; off <<= 1) {
            int x = (tid >= off) ? s[tid - off] : 0;
            __syncthreads();
            s[tid] += x;
            __syncthreads();
        }
        if (i < NN) g_off[i] = carry_s + s[tid] - v;   // exclusive
        __syncthreads();
        if (tid == 0) carry_s += s[1023];
        __syncthreads();
    }
    if (threadIdx.x == 0) g_off[NN] = carry_s;
}

__global__ void k_fill(const void* __restrict__ ei, int E) {
    int i = blockIdx.x * blockDim.x + threadIdx.x;
    if (i < E) {
        long long sl = edge_at(ei, i);
        long long dl = edge_at(ei, (size_t)E + i);
        if (sl < 0 || sl >= NN || dl < 0 || dl >= NN) return;
        int s = (int)sl, d = (int)dl;
        int pos = g_off[d] + atomicAdd(&g_cursor[d], 1);
        g_csr[pos] = make_int2(s, __float_as_int(-g_dinv[s] * g_dinv[d]));
    }
}

// ---------------- gather helper: warp-uniform csr reads, MLP=4 ------------
__device__ __forceinline__ float gather_h(const float* __restrict__ src, int n, int lane) {
    int i = g_off[n], end = g_off[n + 1];
    float a0 = 0.f, a1 = 0.f, a2 = 0.f, a3 = 0.f;
    for (; i + 4 <= end; i += 4) {
        int2 e0 = g_csr[i], e1 = g_csr[i + 1], e2 = g_csr[i + 2], e3 = g_csr[i + 3];
        float v0 = src[e0.x * CH + lane];
        float v1 = src[e1.x * CH + lane];
        float v2 = src[e2.x * CH + lane];
        float v3 = src[e3.x * CH + lane];
        a0 += __int_as_float(e0.y) * v0;
        a1 += __int_as_float(e1.y) * v1;
        a2 += __int_as_float(e2.y) * v2;
        a3 += __int_as_float(e3.y) * v3;
    }
    for (; i < end; i++) {
        int2 e = g_csr[i];
        a0 += __int_as_float(e.y) * src[e.x * CH + lane];
    }
    return (a0 + a1) + (a2 + a3);
}

// ---------------- time-parallel precompute: AX[t,n,:] = agg(x_t)[n] -------
// 8 warps/block; warp = node, half-warps = two timesteps, ch = lane&15.
__global__ void __launch_bounds__(256, 4) k_ax(const float* __restrict__ X) {
    int warp = threadIdx.x >> 5, lane = threadIdx.x & 31;
    int tp = blockIdx.x / (NN / 8);
    int nb = blockIdx.x % (NN / 8);
    int n  = nb * 8 + warp;
    int t  = tp * 2 + (lane >> 4);
    int ch = lane & 15;
    const float* Xt = X + (size_t)t * NN * CIN;

    int i = g_off[n], end = g_off[n + 1];
    float a0 = 0.f, a1 = 0.f, a2 = 0.f, a3 = 0.f;
    for (; i + 4 <= end; i += 4) {
        int2 e0 = g_csr[i], e1 = g_csr[i + 1], e2 = g_csr[i + 2], e3 = g_csr[i + 3];
        a0 += __int_as_float(e0.y) * Xt[e0.x * CIN + ch];
        a1 += __int_as_float(e1.y) * Xt[e1.x * CIN + ch];
        a2 += __int_as_float(e2.y) * Xt[e2.x * CIN + ch];
        a3 += __int_as_float(e3.y) * Xt[e3.x * CIN + ch];
    }
    for (; i < end; i++) {
        int2 e = g_csr[i];
        a0 += __int_as_float(e.y) * Xt[e.x * CIN + ch];
    }
    g_AX[((size_t)t * NN + n) * CIN + ch] = (a0 + a1) + (a2 + a3);
}

// ---------------- recurrence kernels ----------------
// 256 thr = 8 warps/block. Warp handles a node PAIR. Lane = hidden channel.
// Dense matmuls: operand vectors staged in smem, read back as warp-uniform
// LDS.128 quads; 4 weight matrices packed per c into one float4 LDS.

__global__ void __launch_bounds__(256, 4) k_gru_a(
    int t, const float* __restrict__ X,
    const float* __restrict__ Wxz, const float* __restrict__ bxz,
    const float* __restrict__ Whz, const float* __restrict__ bhz,
    const float* __restrict__ Wxr, const float* __restrict__ bxr,
    const float* __restrict__ Whr, const float* __restrict__ bhr)
{
    __shared__ float4 s_wx[CIN * CH];   // {wxz0, wxz1, wxr0, wxr1}[c][j]
    __shared__ float4 s_wh[CH * CH];    // {whz0, whz1, whr0, whr1}[c][j]
    __shared__ float  s_bz[CH], s_br[CH];
    __shared__ __align__(16) float s_st[8][6][CH];  // [warp][hA,aA,hB,aB,xpA,xpB][ch]
    int tid = threadIdx.x;
    for (int i = tid; i < CIN * CH; i += 256)
        s_wx[i] = make_float4(Wxz[i], Wxz[CIN * CH + i], Wxr[i], Wxr[CIN * CH + i]);
    for (int i = tid; i < CH * CH; i += 256)
        s_wh[i] = make_float4(Whz[i], Whz[CH * CH + i], Whr[i], Whr[CH * CH + i]);
    if (tid < CH) { s_bz[tid] = bxz[tid] + bhz[tid]; s_br[tid] = bxr[tid] + bhr[tid]; }
    __syncthreads();

    int lane = tid & 31, wid = tid >> 5;
    int gw = blockIdx.x * 8 + wid, nw = gridDim.x * 8;
    for (int p = gw; p < NN / 2; p += nw) {
        int nA = 2 * p, nB = 2 * p + 1;
        float hA = g_h[nA * CH + lane];
        float hB = g_h[nB * CH + lane];
        // packed x-side vector: [0..15]=x, [16..31]=agg(x)
        int cx = lane & 15;
        float xpA, xpB;
        if (lane < 16) {
            xpA = X[((size_t)t * NN + nA) * CIN + cx];
            xpB = X[((size_t)t * NN + nB) * CIN + cx];
        } else {
            xpA = g_AX[((size_t)t * NN + nA) * CIN + cx];
            xpB = g_AX[((size_t)t * NN + nB) * CIN + cx];
        }
        float aA = gather_h(g_h, nA, lane);
        float aB = gather_h(g_h, nB, lane);

        s_st[wid][0][lane] = hA;  s_st[wid][1][lane] = aA;
        s_st[wid][2][lane] = hB;  s_st[wid][3][lane] = aB;
        s_st[wid][4][lane] = xpA; s_st[wid][5][lane] = xpB;
        __syncwarp();

        float zA = s_bz[lane], rA = s_br[lane];
        float zB = zA,         rB = rA;

        const float4* hAp  = (const float4*)&s_st[wid][0][0];
        const float4* aAp  = (const float4*)&s_st[wid][1][0];
        const float4* hBp  = (const float4*)&s_st[wid][2][0];
        const float4* aBp  = (const float4*)&s_st[wid][3][0];
        const float4* xAp  = (const float4*)&s_st[wid][4][0];
        const float4* xBp  = (const float4*)&s_st[wid][5][0];

        // x side: c in 0..15 ; x at quad c4, agg(x) at quad 4+c4
#pragma unroll
        for (int c4 = 0; c4 < 4; c4++) {
            float4 x4A = xAp[c4], ax4A = xAp[4 + c4];
            float4 x4B = xBp[c4], ax4B = xBp[4 + c4];
#pragma unroll
            for (int u = 0; u < 4; u++) {
                float4 w = s_wx[(c4 * 4 + u) * CH + lane];
                float xa = GETC(x4A, u), aa = GETC(ax4A, u);
                float xb = GETC(x4B, u), ab = GETC(ax4B, u);
                zA += xa * w.x + aa * w.y;  rA += xa * w.z + aa * w.w;
                zB += xb * w.x + ab * w.y;  rB += xb * w.z + ab * w.w;
            }
        }
        // h side: c in 0..31
#pragma unroll
        for (int c4 = 0; c4 < 8; c4++) {
            float4 h4A = hAp[c4], a4A = aAp[c4];
            float4 h4B = hBp[c4], a4B = aBp[c4];
#pragma unroll
            for (int u = 0; u < 4; u++) {
                float4 w = s_wh[(c4 * 4 + u) * CH + lane];
                float ha = GETC(h4A, u), aa = GETC(a4A, u);
                float hb = GETC(h4B, u), ab = GETC(a4B, u);
                zA += ha * w.x + aa * w.y;  rA += ha * w.z + aa * w.w;
                zB += hb * w.x + ab * w.y;  rB += hb * w.z + ab * w.w;
            }
        }
        zA = 1.f / (1.f + __expf(-zA));
        rA = 1.f / (1.f + __expf(-rA));
        zB = 1.f / (1.f + __expf(-zB));
        rB = 1.f / (1.f + __expf(-rB));
        g_Z [nA * CH + lane] = zA;  g_hR[nA * CH + lane] = hA * rA;
        g_Z [nB * CH + lane] = zB;  g_hR[nB * CH + lane] = hB * rB;
        __syncwarp();
    }
}

__global__ void __launch_bounds__(256, 4) k_gru_b(
    int t, const float* __restrict__ X,
    const float* __restrict__ Wxh, const float* __restrict__ bxh,
    const float* __restrict__ Whh, const float* __restrict__ bhh,
    const float* __restrict__ fcw, const float* __restrict__ fcb,
    float* __restrict__ out)
{
    __shared__ float2 s_wx[CIN * CH];   // {wxh0, wxh1}
    __shared__ float2 s_wh[CH * CH];    // {whh0, whh1}
    __shared__ float  s_fcw[CH * COUTC];
    __shared__ float  s_bh[CH];
    __shared__ float  s_fcb[COUTC];
    __shared__ __align__(16) float s_st[8][8][CH];  // [hrA,aA,hrB,aB,xpA,xpB,hnA,hnB]
    int tid = threadIdx.x;
    for (int i = tid; i < CIN * CH; i += 256)
        s_wx[i] = make_float2(Wxh[i], Wxh[CIN * CH + i]);
    for (int i = tid; i < CH * CH; i += 256)
        s_wh[i] = make_float2(Whh[i], Whh[CH * CH + i]);
    for (int i = tid; i < CH * COUTC; i += 256) s_fcw[i] = fcw[i];
    if (tid < CH)    s_bh[tid]  = bxh[tid] + bhh[tid];
    if (tid < COUTC) s_fcb[tid] = fcb[tid];
    __syncthreads();

    int lane = tid & 31, wid = tid >> 5;
    int gw = blockIdx.x * 8 + wid, nw = gridDim.x * 8;
    for (int p = gw; p < NN / 2; p += nw) {
        int nA = 2 * p, nB = 2 * p + 1;
        float hA  = g_h [nA * CH + lane];
        float hB  = g_h [nB * CH + lane];
        float hrA = g_hR[nA * CH + lane];
        float hrB = g_hR[nB * CH + lane];
        float zA  = g_Z [nA * CH + lane];
        float zB  = g_Z [nB * CH + lane];
        int cx = lane & 15;
        float xpA, xpB;
        if (lane < 16) {
            xpA = X[((size_t)t * NN + nA) * CIN + cx];
            xpB = X[((size_t)t * NN + nB) * CIN + cx];
        } else {
            xpA = g_AX[((size_t)t * NN + nA) * CIN + cx];
            xpB = g_AX[((size_t)t * NN + nB) * CIN + cx];
        }
        float aA = gather_h(g_hR, nA, lane);
        float aB = gather_h(g_hR, nB, lane);

        s_st[wid][0][lane] = hrA; s_st[wid][1][lane] = aA;
        s_st[wid][2][lane] = hrB; s_st[wid][3][lane] = aB;
        s_st[wid][4][lane] = xpA; s_st[wid][5][lane] = xpB;
        __syncwarp();

        float cA = s_bh[lane], cB = cA;
        const float4* hAp = (const float4*)&s_st[wid][0][0];
        const float4* aAp = (const float4*)&s_st[wid][1][0];
        const float4* hBp = (const float4*)&s_st[wid][2][0];
        const float4* aBp = (const float4*)&s_st[wid][3][0];
        const float4* xAp = (const float4*)&s_st[wid][4][0];
        const float4* xBp = (const float4*)&s_st[wid][5][0];

#pragma unroll
        for (int c4 = 0; c4 < 4; c4++) {
            float4 x4A = xAp[c4], ax4A = xAp[4 + c4];
            float4 x4B = xBp[c4], ax4B = xBp[4 + c4];
#pragma unroll
            for (int u = 0; u < 4; u++) {
                float2 w = s_wx[(c4 * 4 + u) * CH + lane];
                cA += GETC(x4A, u) * w.x + GETC(ax4A, u) * w.y;
                cB += GETC(x4B, u) * w.x + GETC(ax4B, u) * w.y;
            }
        }
#pragma unroll
        for (int c4 = 0; c4 < 8; c4++) {
            float4 h4A = hAp[c4], a4A = aAp[c4];
            float4 h4B = hBp[c4], a4B = aBp[c4];
#pragma unroll
            for (int u = 0; u < 4; u++) {
                float2 w = s_wh[(c4 * 4 + u) * CH + lane];
                cA += GETC(h4A, u) * w.x + GETC(a4A, u) * w.y;
                cB += GETC(h4B, u) * w.x + GETC(a4B, u) * w.y;
            }
        }
        float hnA = zA * hA + (1.f - zA) * tanhf(cA);
        float hnB = zB * hB + (1.f - zB) * tanhf(cB);
        g_h[nA * CH + lane] = hnA;
        g_h[nB * CH + lane] = hnB;

        // out = hn @ fc_w + fc_b : lanes 0..7 -> node A, lanes 8..15 -> node B
        s_st[wid][6][lane] = hnA;
        s_st[wid][7][lane] = hnB;
        __syncwarp();
        if (lane < 16) {
            int node = lane >> 3, j = lane & 7;
            const float* hn = &s_st[wid][6 + node][0];
            float acc = s_fcb[j];
#pragma unroll
            for (int c = 0; c < CH; c++) acc += hn[c] * s_fcw[c * COUTC + j];
            int n = node ? nB : nA;
            out[((size_t)t * NN + n) * COUTC + j] = acc;
        }
        __syncwarp();
    }
}

// ---------------- launch ----------------
extern "C" void kernel_launch(void* const* d_in, const int* in_sizes, int n_in,
                              void* d_out, int out_size) {
    const float* X   = (const float*)d_in[0];
    const void*  ei  = d_in[1];
    const float* Wxz = (const float*)d_in[2];
    const float* bxz = (const float*)d_in[3];
    const float* Whz = (const float*)d_in[4];
    const float* bhz = (const float*)d_in[5];
    const float* Wxr = (const float*)d_in[6];
    const float* bxr = (const float*)d_in[7];
    const float* Whr = (const float*)d_in[8];
    const float* bhr = (const float*)d_in[9];
    const float* Wxh = (const float*)d_in[10];
    const float* bxh = (const float*)d_in[11];
    const float* Whh = (const float*)d_in[12];
    const float* bhh = (const float*)d_in[13];
    const float* fcw = (const float*)d_in[14];
    const float* fcb = (const float*)d_in[15];
    float* out = (float*)d_out;

    int E = in_sizes[1] / 2;

    // preprocess (5 launches, so the 6th = first k_gru_a gets profiled by ncu)
    k_zero<<<2048, 256>>>(ei);
    k_count<<<(E + 255) / 256, 256>>>(ei, E);
    k_scan<<<1, 1024>>>();
    k_fill<<<(E + 255) / 256, 256>>>(ei, E);
    k_ax<<<(TT / 2) * (NN / 8), 256>>>(X);

    // sequential GRU recurrence
    for (int t = 0; t < TT; t++) {
        k_gru_a<<<592, 256>>>(t, X, Wxz, bxz, Whz, bhz, Wxr, bxr, Whr, bhr);
        k_gru_b<<<592, 256>>>(t, X, Wxh, bxh, Whh, bhh, fcw, fcb, out);
    }
}